// round 12
// baseline (speedup 1.0000x reference)
#include <cuda_runtime.h>
#include <cuda_fp16.h>
#include <math.h>
#include <stdint.h>

#define TOK 8192
#define DIM 1024
#define NE  16
#define NTILE 144           // expert row-block grid.y (>= 16384/128 + 16)
#define EGRID (8 * NTILE)   // total expert-gemm CTAs

// ---------------- device scratch (static, allocation-free; zero at load) ----------
__device__ __align__(1024) __half g_wsh[DIM * DIM];         // folded shared weight fp16
__device__ __align__(1024) __half g_xh[TOK * DIM];          // fp16 feat
__device__ __align__(1024) __half g_ewh[NE * DIM * DIM];    // fp16 expert weights
__device__ int   g_ecount[NE];
__device__ float g_pi[NE];
__device__ int   g_cnt[NE];
__device__ int   g_etok[NE * TOK];
__device__ float g_ewt[NE * TOK];
__device__ int   g_done;

__device__ __forceinline__ uint32_t smem_u32(const void* p) {
    uint32_t a;
    asm("{ .reg .u64 t; cvta.to.shared.u64 t, %1; cvt.u32.u64 %0, t; }" : "=r"(a) : "l"(p));
    return a;
}

#define CP16(dst, src) \
    asm volatile("cp.async.cg.shared.global [%0], [%1], 16;" :: "r"(dst), "l"(src) : "memory")
#define CP_COMMIT() asm volatile("cp.async.commit_group;" ::: "memory")
#define CP_WAIT1()  asm volatile("cp.async.wait_group 1;" ::: "memory")

// ---------------- fused prep + router: 256 blocks x 512 threads, 32 tok/block -----
__global__ void __launch_bounds__(512) k_main(const float* __restrict__ x,
                                              const float* __restrict__ rw,
                                              const float* __restrict__ sw,
                                              const float* __restrict__ ew) {
    __shared__ float srw[NE * DIM];
    __shared__ float s_pi[NE];
    __shared__ int   s_cnt[NE];
    int tid = threadIdx.x;
    int bid = blockIdx.x;
    if (tid < NE) { s_pi[tid] = 0.f; s_cnt[tid] = 0; }
    for (int i = tid; i < NE * DIM; i += 512) srw[i] = rw[i];

    // prep slice: expert weights -> fp16 (32 float4 per thread)
    const float4* e4 = (const float4*)ew;
#pragma unroll 8
    for (int j = 0; j < 32; ++j) {
        int i = bid * 16384 + j * 512 + tid;
        float4 v = e4[i];
        ((__half2*)g_ewh)[2 * i] = __floats2half2_rn(v.x, v.y);
        ((__half2*)g_ewh)[2 * i + 1] = __floats2half2_rn(v.z, v.w);
    }
    // prep slice: folded shared weight -> fp16 (2 float4 per thread)
#pragma unroll
    for (int j = 0; j < 2; ++j) {
        int i = bid * 1024 + j * 512 + tid;
        const float4* s4 = (const float4*)sw;
        float4 a = s4[i];
        float4 b = s4[i + (DIM * DIM) / 4];
        ((__half2*)g_wsh)[2 * i] = __floats2half2_rn(a.x + b.x, a.y + b.y);
        ((__half2*)g_wsh)[2 * i + 1] = __floats2half2_rn(a.z + b.z, a.w + b.w);
    }
    __syncthreads();

    // router: each warp handles two tokens
    int warp = tid >> 5, lane = tid & 31;
#pragma unroll
    for (int rep = 0; rep < 2; ++rep) {
        int t = bid * 32 + warp * 2 + rep;
        const float2* xr = (const float2*)(x + (size_t)t * DIM);

        float2 xv[16];
#pragma unroll
        for (int j = 0; j < 16; ++j) xv[j] = xr[lane + 32 * j];

        __half2* xo = (__half2*)g_xh + (size_t)t * (DIM / 2);
#pragma unroll
        for (int j = 0; j < 16; ++j)
            xo[lane + 32 * j] = __floats2half2_rn(xv[j].x, xv[j].y);

        float logit[NE];
#pragma unroll
        for (int e = 0; e < NE; ++e) {
            const float2* w = (const float2*)(srw + e * DIM);
            float s = 0.f;
#pragma unroll
            for (int j = 0; j < 16; ++j) {
                float2 wv = w[lane + 32 * j];
                s += xv[j].x * wv.x + xv[j].y * wv.y;
            }
#pragma unroll
            for (int o = 16; o > 0; o >>= 1) s += __shfl_xor_sync(0xffffffffu, s, o);
            logit[e] = s;
        }

        int e1 = 0; float v1 = logit[0];
#pragma unroll
        for (int e = 1; e < NE; ++e) if (logit[e] > v1) { v1 = logit[e]; e1 = e; }
        int e2 = -1; float v2 = -3.4e38f;
#pragma unroll
        for (int e = 0; e < NE; ++e) if (e != e1 && logit[e] > v2) { v2 = logit[e]; e2 = e; }

        float w1 = 1.f / (1.f + expf(v2 - v1));
        float w2 = 1.f - w1;

        float se = 0.f;
#pragma unroll
        for (int e = 0; e < NE; ++e) se += expf(logit[e] - v1);
        float inv_se = 1.f / se;

        if (lane == 0) {
            atomicAdd(&s_cnt[e1], 1);
            atomicAdd(&s_cnt[e2], 1);
            int p1 = atomicAdd(&g_ecount[e1], 1);
            int p2 = atomicAdd(&g_ecount[e2], 1);
            g_etok[e1 * TOK + p1] = t;  g_ewt[e1 * TOK + p1] = w1;
            g_etok[e2 * TOK + p2] = t;  g_ewt[e2 * TOK + p2] = w2;
#pragma unroll
            for (int e = 0; e < NE; ++e)
                atomicAdd(&s_pi[e], expf(logit[e] - v1) * inv_se);
        }
    }
    __syncthreads();
    if (tid < NE) {
        atomicAdd(&g_pi[tid], s_pi[tid]);
        atomicAdd(&g_cnt[tid], s_cnt[tid]);
    }
}

// ---------------- fp16 mma.sync GEMM: 128 threads, warp tile 64x64 ----------------
#define RSTRB   144
#define A_BYTES (128 * RSTRB)
#define STG_B   (2 * A_BYTES)
#define NSTG    3
#define SMEM_SZ (NSTG * STG_B)
#define NK      (DIM / 64)

#define LD_FRAGS(buf, stgbase, sub)                                                   \
    do {                                                                              \
        uint32_t _sg = (stgbase);                                                     \
        _Pragma("unroll")                                                             \
        for (int mt = 0; mt < 4; ++mt) {                                              \
            uint32_t addr = _sg + aA0 + (uint32_t)(mt * 16 * RSTRB + (sub) * 32);     \
            asm volatile("ldmatrix.sync.aligned.m8n8.x4.shared.b16 {%0,%1,%2,%3}, [%4];" \
                : "=r"(af[buf][mt][0]), "=r"(af[buf][mt][1]),                         \
                  "=r"(af[buf][mt][2]), "=r"(af[buf][mt][3])                          \
                : "r"(addr));                                                         \
        }                                                                             \
        _Pragma("unroll")                                                             \
        for (int p = 0; p < 4; ++p) {                                                 \
            uint32_t addr = _sg + aB0 + (uint32_t)(p * 16 * RSTRB + (sub) * 32);      \
            asm volatile("ldmatrix.sync.aligned.m8n8.x4.shared.b16 {%0,%1,%2,%3}, [%4];" \
                : "=r"(bf[buf][2 * p][0]), "=r"(bf[buf][2 * p][1]),                   \
                  "=r"(bf[buf][2 * p + 1][0]), "=r"(bf[buf][2 * p + 1][1])            \
                : "r"(addr));                                                         \
        }                                                                             \
    } while (0)

#define DO_MMAS(buf)                                                                  \
    do {                                                                              \
        _Pragma("unroll")                                                             \
        for (int mt = 0; mt < 4; ++mt)                                                \
            _Pragma("unroll")                                                         \
            for (int nt = 0; nt < 8; ++nt) {                                          \
                asm volatile(                                                         \
                    "mma.sync.aligned.m16n8k16.row.col.f32.f16.f16.f32 "              \
                    "{%0,%1,%2,%3}, {%4,%5,%6,%7}, {%8,%9}, {%0,%1,%2,%3};"           \
                    : "+f"(acc[mt][nt][0]), "+f"(acc[mt][nt][1]),                     \
                      "+f"(acc[mt][nt][2]), "+f"(acc[mt][nt][3])                      \
                    : "r"(af[buf][mt][0]), "r"(af[buf][mt][1]),                       \
                      "r"(af[buf][mt][2]), "r"(af[buf][mt][3]),                       \
                      "r"(bf[buf][nt][0]), "r"(bf[buf][nt][1]));                      \
            }                                                                         \
    } while (0)

#define ISSUE_STAGE(stgbuf, kb)                                                       \
    do {                                                                              \
        uint32_t so = sb + (uint32_t)((stgbuf) * STG_B);                              \
        _Pragma("unroll")                                                             \
        for (int i = 0; i < 8; ++i) {                                                 \
            CP16(so + dA0 + (uint32_t)(i * 16 * RSTRB),                               \
                 (const char*)g_xh + Aoff[i] + (kb));                                 \
            CP16(so + (uint32_t)A_BYTES + dA0 + (uint32_t)(i * 16 * RSTRB),           \
                 Bp + (size_t)i * 32768 + (kb));                                      \
        }                                                                             \
    } while (0)

__device__ __forceinline__ void finish_expert_cta(int tid) {
    if (tid == 0) {
        int v = atomicAdd(&g_done, 1);
        if (v == EGRID - 1) {
            // last CTA of the whole expert grid: reset state for the next replay
            atomicExch(&g_done, 0);
#pragma unroll
            for (int e = 0; e < NE; ++e) {
                g_ecount[e] = 0;
                g_pi[e] = 0.f;
                g_cnt[e] = 0;
            }
        }
    }
}

template <bool SHARED>
__global__ void __launch_bounds__(128, 2) k_gemm(float* __restrict__ out,
                                                 float* __restrict__ aux_dst) {
    int tid = threadIdx.x;
    int g, n, row0;
    if (SHARED) {
        if (blockIdx.x == 0 && blockIdx.y == 0 && tid == 0) {
            float a = 0.f;
#pragma unroll
            for (int e = 0; e < NE; ++e)
                a += (g_pi[e] / (float)TOK) * ((float)g_cnt[e] / (float)TOK);
            *aux_dst = a;
        }
        g = NE; n = TOK; row0 = blockIdx.y * 128;
    } else {
        int ty = blockIdx.y;
        g = -1; row0 = 0;
        int cum = 0;
#pragma unroll
        for (int e = 0; e < NE; ++e) {
            int ne = g_ecount[e];
            int nb = (ne + 127) >> 7;
            if (g < 0 && ty < cum + nb) { g = e; row0 = (ty - cum) << 7; }
            cum += nb;
        }
        if (g < 0) { finish_expert_cta(tid); return; }
        n = g_ecount[g];
    }
    int col0 = blockIdx.x * 128;

    const __half* Bbase = SHARED ? (g_wsh + (size_t)col0 * DIM)
                                 : (g_ewh + (size_t)g * DIM * DIM + (size_t)col0 * DIM);

    extern __shared__ __align__(1024) char smem[];
    uint32_t sb = smem_u32(smem);
    int wid = tid >> 5, lane = tid & 31;
    int wm = wid & 1, wn = wid >> 1;       // 2x2 warp grid, warp tile 64x64

    int ldrow = tid >> 3;                  // 0..15
    int ldch = (tid & 7) * 16;
    uint32_t dA0 = (uint32_t)(ldrow * RSTRB + ldch);

    // A source offsets into g_xh (bytes); ragged tail clamped (results never stored)
    uint32_t Aoff[8];
#pragma unroll
    for (int i = 0; i < 8; ++i) {
        int r = row0 + ldrow + i * 16;
        int rc = (r < n) ? r : (n - 1);
        int t = SHARED ? r : g_etok[g * TOK + rc];
        Aoff[i] = (uint32_t)t * 2048u + (uint32_t)ldch;
    }
    const char* Bp = (const char*)Bbase + (size_t)ldrow * 2048 + ldch;

    int rA = lane & 15, cAb = lane >> 4;
    uint32_t aA0 = (uint32_t)(((wm * 64 + rA) * RSTRB) + cAb * 16);
    int rB = (lane & 7) + ((lane >> 4) << 3), cBb = (lane >> 3) & 1;
    uint32_t aB0 = (uint32_t)A_BYTES + (uint32_t)(((wn * 64 + rB) * RSTRB) + cBb * 16);

    float acc[4][8][4];
#pragma unroll
    for (int i = 0; i < 4; ++i)
#pragma unroll
        for (int j = 0; j < 8; ++j)
#pragma unroll
            for (int k = 0; k < 4; ++k) acc[i][j][k] = 0.f;

    uint32_t af[2][4][4];
    uint32_t bf[2][8][2];

    // prologue
    ISSUE_STAGE(0, 0);
    CP_COMMIT();
    ISSUE_STAGE(1, 128);
    CP_COMMIT();
    CP_WAIT1();
    __syncthreads();
    LD_FRAGS(0, sb, 0);

    for (int ks = 0; ks < NK; ++ks) {
        if (ks + 2 < NK) ISSUE_STAGE((ks + 2) % NSTG, (ks + 2) * 128);
        CP_COMMIT();

        uint32_t stg = sb + (uint32_t)((ks % NSTG) * STG_B);
#pragma unroll
        for (int sub = 0; sub < 4; ++sub) {
            int cur = sub & 1, nxt = cur ^ 1;
            if (sub < 3) {
                LD_FRAGS(nxt, stg, sub + 1);
            } else if (ks + 1 < NK) {
                CP_WAIT1();
                __syncthreads();
                LD_FRAGS(nxt, sb + (uint32_t)(((ks + 1) % NSTG) * STG_B), 0);
            }
            DO_MMAS(cur);
        }
    }

    // epilogue: shared = plain stores (runs first), experts = atomicAdd on top
    int t4 = lane >> 2, t2 = lane & 3;
#pragma unroll
    for (int mt = 0; mt < 4; ++mt) {
#pragma unroll
        for (int h = 0; h < 2; ++h) {
            int r = row0 + wm * 64 + mt * 16 + h * 8 + t4;
            if (SHARED) {
                float* dst = out + (size_t)r * DIM + col0 + wn * 64 + t2 * 2;
#pragma unroll
                for (int nt = 0; nt < 8; ++nt)
                    *(float2*)(dst + nt * 8) =
                        make_float2(acc[mt][nt][2 * h], acc[mt][nt][2 * h + 1]);
            } else if (r < n) {
                int tok = g_etok[g * TOK + r];
                float wt = g_ewt[g * TOK + r];
                float* dst = out + (size_t)tok * DIM + col0 + wn * 64 + t2 * 2;
#pragma unroll
                for (int nt = 0; nt < 8; ++nt) {
                    atomicAdd(dst + nt * 8,     acc[mt][nt][2 * h] * wt);
                    atomicAdd(dst + nt * 8 + 1, acc[mt][nt][2 * h + 1] * wt);
                }
            }
        }
    }

    if (!SHARED) {
        __syncthreads();            // all threads done reading router state
        finish_expert_cta(tid);
    }
}

// ---------------- launch ----------------
extern "C" void kernel_launch(void* const* d_in, const int* in_sizes, int n_in,
                              void* d_out, int out_size) {
    const float* feat = (const float*)d_in[0];
    const float* rw   = (const float*)d_in[1];
    const float* sw   = (const float*)d_in[2];
    const float* ew   = (const float*)d_in[3];
    float* out = (float*)d_out;
    float* aux = out + (out_size - 1);

    cudaFuncSetAttribute(k_gemm<true>, cudaFuncAttributeMaxDynamicSharedMemorySize, SMEM_SZ);
    cudaFuncSetAttribute(k_gemm<false>, cudaFuncAttributeMaxDynamicSharedMemorySize, SMEM_SZ);

    k_main<<<256, 512>>>(feat, rw, sw, ew);
    k_gemm<true><<<dim3(DIM / 128, TOK / 128), 128, SMEM_SZ>>>(out, aux);
    k_gemm<false><<<dim3(DIM / 128, NTILE), 128, SMEM_SZ>>>(out, aux);
}

// round 13
// speedup vs baseline: 1.0283x; 1.0283x over previous
#include <cuda_runtime.h>
#include <cuda_fp16.h>
#include <math.h>
#include <stdint.h>

#define TOK 8192
#define DIM 1024
#define NE  16
#define NTILE 144           // expert row-block grid.y (>= 16384/128 + 16)
#define EGRID (8 * NTILE)   // total expert-gemm CTAs

// ---------------- device scratch (static, allocation-free; zero at load) ----------
__device__ __align__(1024) __half g_wsh[DIM * DIM];         // folded shared weight fp16
__device__ __align__(1024) __half g_xh[TOK * DIM];          // fp16 feat
__device__ __align__(1024) __half g_ewh[NE * DIM * DIM];    // fp16 expert weights
__device__ int   g_ecount[NE];
__device__ float g_pi[NE];
__device__ int   g_cnt[NE];
__device__ int   g_etok[NE * TOK];
__device__ float g_ewt[NE * TOK];
__device__ int   g_done;

__device__ __forceinline__ uint32_t smem_u32(const void* p) {
    uint32_t a;
    asm("{ .reg .u64 t; cvta.to.shared.u64 t, %1; cvt.u32.u64 %0, t; }" : "=r"(a) : "l"(p));
    return a;
}

#define CP16(dst, src) \
    asm volatile("cp.async.cg.shared.global [%0], [%1], 16;" :: "r"(dst), "l"(src) : "memory")
#define CP_COMMIT() asm volatile("cp.async.commit_group;" ::: "memory")
#define CP_WAIT1()  asm volatile("cp.async.wait_group 1;" ::: "memory")

// ---------------- streaming prep: ew -> fp16, wsum fold. 2176 blocks x 256 thr ----
__global__ void __launch_bounds__(256) k_prep(const float* __restrict__ sw,
                                              const float* __restrict__ ew) {
    int bid = blockIdx.x, tid = threadIdx.x;
    if (bid < 2048) {
        // 2048 float4 per block, 8 per thread
        const float4* e4 = (const float4*)ew + (size_t)bid * 2048;
        __half2* o = (__half2*)g_ewh + (size_t)bid * 4096;
#pragma unroll
        for (int j = 0; j < 8; ++j) {
            int i = j * 256 + tid;
            float4 v = e4[i];
            o[2 * i] = __floats2half2_rn(v.x, v.y);
            o[2 * i + 1] = __floats2half2_rn(v.z, v.w);
        }
    } else {
        int b = bid - 2048;                 // 0..127, fold shared weight
        const float4* s4 = (const float4*)sw + (size_t)b * 2048;
        const float4* s4b = s4 + (DIM * DIM) / 4;
        __half2* o = (__half2*)g_wsh + (size_t)b * 4096;
#pragma unroll
        for (int j = 0; j < 8; ++j) {
            int i = j * 256 + tid;
            float4 a = s4[i];
            float4 c = s4b[i];
            o[2 * i] = __floats2half2_rn(a.x + c.x, a.y + c.y);
            o[2 * i + 1] = __floats2half2_rn(a.z + c.z, a.w + c.w);
        }
    }
}

// ---------------- router: 512 blocks x 512 threads, 16 tok/block ----------------
__global__ void __launch_bounds__(512) k_router(const float* __restrict__ x,
                                                const float* __restrict__ rw) {
    __shared__ float srw[NE * DIM];
    __shared__ float s_pi[NE];
    __shared__ int   s_cnt[NE];
    int tid = threadIdx.x;
    if (tid < NE) { s_pi[tid] = 0.f; s_cnt[tid] = 0; }
    for (int i = tid; i < NE * DIM; i += 512) srw[i] = rw[i];
    __syncthreads();

    int warp = tid >> 5, lane = tid & 31;
    int t = blockIdx.x * 16 + warp;
    const float2* xr = (const float2*)(x + (size_t)t * DIM);

    float2 xv[16];
#pragma unroll
    for (int j = 0; j < 16; ++j) xv[j] = xr[lane + 32 * j];

    __half2* xo = (__half2*)g_xh + (size_t)t * (DIM / 2);
#pragma unroll
    for (int j = 0; j < 16; ++j)
        xo[lane + 32 * j] = __floats2half2_rn(xv[j].x, xv[j].y);

    float logit[NE];
#pragma unroll
    for (int e = 0; e < NE; ++e) {
        const float2* w = (const float2*)(srw + e * DIM);
        float s = 0.f;
#pragma unroll
        for (int j = 0; j < 16; ++j) {
            float2 wv = w[lane + 32 * j];
            s += xv[j].x * wv.x + xv[j].y * wv.y;
        }
#pragma unroll
        for (int o = 16; o > 0; o >>= 1) s += __shfl_xor_sync(0xffffffffu, s, o);
        logit[e] = s;
    }

    int e1 = 0; float v1 = logit[0];
#pragma unroll
    for (int e = 1; e < NE; ++e) if (logit[e] > v1) { v1 = logit[e]; e1 = e; }
    int e2 = -1; float v2 = -3.4e38f;
#pragma unroll
    for (int e = 0; e < NE; ++e) if (e != e1 && logit[e] > v2) { v2 = logit[e]; e2 = e; }

    float w1 = 1.f / (1.f + expf(v2 - v1));
    float w2 = 1.f - w1;

    float se = 0.f;
#pragma unroll
    for (int e = 0; e < NE; ++e) se += expf(logit[e] - v1);
    float inv_se = 1.f / se;

    if (lane == 0) {
        atomicAdd(&s_cnt[e1], 1);
        atomicAdd(&s_cnt[e2], 1);
        int p1 = atomicAdd(&g_ecount[e1], 1);
        int p2 = atomicAdd(&g_ecount[e2], 1);
        g_etok[e1 * TOK + p1] = t;  g_ewt[e1 * TOK + p1] = w1;
        g_etok[e2 * TOK + p2] = t;  g_ewt[e2 * TOK + p2] = w2;
#pragma unroll
        for (int e = 0; e < NE; ++e)
            atomicAdd(&s_pi[e], expf(logit[e] - v1) * inv_se);
    }
    __syncthreads();
    if (tid < NE) {
        atomicAdd(&g_pi[tid], s_pi[tid]);
        atomicAdd(&g_cnt[tid], s_cnt[tid]);
    }
}

// ---------------- fp16 mma.sync GEMM: 128 threads, warp tile 64x64 ----------------
#define RSTRB   144
#define A_BYTES (128 * RSTRB)
#define STG_B   (2 * A_BYTES)
#define NSTG    3
#define SMEM_SZ (NSTG * STG_B)
#define NK      (DIM / 64)

#define LD_FRAGS(buf, stgbase, sub)                                                   \
    do {                                                                              \
        uint32_t _sg = (stgbase);                                                     \
        _Pragma("unroll")                                                             \
        for (int mt = 0; mt < 4; ++mt) {                                              \
            uint32_t addr = _sg + aA0 + (uint32_t)(mt * 16 * RSTRB + (sub) * 32);     \
            asm volatile("ldmatrix.sync.aligned.m8n8.x4.shared.b16 {%0,%1,%2,%3}, [%4];" \
                : "=r"(af[buf][mt][0]), "=r"(af[buf][mt][1]),                         \
                  "=r"(af[buf][mt][2]), "=r"(af[buf][mt][3])                          \
                : "r"(addr));                                                         \
        }                                                                             \
        _Pragma("unroll")                                                             \
        for (int p = 0; p < 4; ++p) {                                                 \
            uint32_t addr = _sg + aB0 + (uint32_t)(p * 16 * RSTRB + (sub) * 32);      \
            asm volatile("ldmatrix.sync.aligned.m8n8.x4.shared.b16 {%0,%1,%2,%3}, [%4];" \
                : "=r"(bf[buf][2 * p][0]), "=r"(bf[buf][2 * p][1]),                   \
                  "=r"(bf[buf][2 * p + 1][0]), "=r"(bf[buf][2 * p + 1][1])            \
                : "r"(addr));                                                         \
        }                                                                             \
    } while (0)

#define DO_MMAS(buf)                                                                  \
    do {                                                                              \
        _Pragma("unroll")                                                             \
        for (int mt = 0; mt < 4; ++mt)                                                \
            _Pragma("unroll")                                                         \
            for (int nt = 0; nt < 8; ++nt) {                                          \
                asm volatile(                                                         \
                    "mma.sync.aligned.m16n8k16.row.col.f32.f16.f16.f32 "              \
                    "{%0,%1,%2,%3}, {%4,%5,%6,%7}, {%8,%9}, {%0,%1,%2,%3};"           \
                    : "+f"(acc[mt][nt][0]), "+f"(acc[mt][nt][1]),                     \
                      "+f"(acc[mt][nt][2]), "+f"(acc[mt][nt][3])                      \
                    : "r"(af[buf][mt][0]), "r"(af[buf][mt][1]),                       \
                      "r"(af[buf][mt][2]), "r"(af[buf][mt][3]),                       \
                      "r"(bf[buf][nt][0]), "r"(bf[buf][nt][1]));                      \
            }                                                                         \
    } while (0)

#define ISSUE_STAGE(stgbuf, kb)                                                       \
    do {                                                                              \
        uint32_t so = sb + (uint32_t)((stgbuf) * STG_B);                              \
        _Pragma("unroll")                                                             \
        for (int i = 0; i < 8; ++i) {                                                 \
            CP16(so + dA0 + (uint32_t)(i * 16 * RSTRB),                               \
                 (const char*)g_xh + Aoff[i] + (kb));                                 \
            CP16(so + (uint32_t)A_BYTES + dA0 + (uint32_t)(i * 16 * RSTRB),           \
                 Bp + (size_t)i * 32768 + (kb));                                      \
        }                                                                             \
    } while (0)

__device__ __forceinline__ void finish_expert_cta(int tid) {
    if (tid == 0) {
        int v = atomicAdd(&g_done, 1);
        if (v == EGRID - 1) {
            atomicExch(&g_done, 0);
#pragma unroll
            for (int e = 0; e < NE; ++e) {
                g_ecount[e] = 0;
                g_pi[e] = 0.f;
                g_cnt[e] = 0;
            }
        }
    }
}

template <bool SHARED>
__global__ void __launch_bounds__(128, 2) k_gemm(float* __restrict__ out,
                                                 float* __restrict__ aux_dst) {
    int tid = threadIdx.x;
    int g, n, row0;
    if (SHARED) {
        if (blockIdx.x == 0 && blockIdx.y == 0 && tid == 0) {
            float a = 0.f;
#pragma unroll
            for (int e = 0; e < NE; ++e)
                a += (g_pi[e] / (float)TOK) * ((float)g_cnt[e] / (float)TOK);
            *aux_dst = a;
        }
        g = NE; n = TOK; row0 = blockIdx.y * 128;
    } else {
        int ty = blockIdx.y;
        g = -1; row0 = 0;
        int cum = 0;
#pragma unroll
        for (int e = 0; e < NE; ++e) {
            int ne = g_ecount[e];
            int nb = (ne + 127) >> 7;
            if (g < 0 && ty < cum + nb) { g = e; row0 = (ty - cum) << 7; }
            cum += nb;
        }
        if (g < 0) { finish_expert_cta(tid); return; }
        n = g_ecount[g];
    }
    int col0 = blockIdx.x * 128;

    const __half* Bbase = SHARED ? (g_wsh + (size_t)col0 * DIM)
                                 : (g_ewh + (size_t)g * DIM * DIM + (size_t)col0 * DIM);

    extern __shared__ __align__(1024) char smem[];
    uint32_t sb = smem_u32(smem);
    int wid = tid >> 5, lane = tid & 31;
    int wm = wid & 1, wn = wid >> 1;       // 2x2 warp grid, warp tile 64x64

    int ldrow = tid >> 3;                  // 0..15
    int ldch = (tid & 7) * 16;
    uint32_t dA0 = (uint32_t)(ldrow * RSTRB + ldch);

    uint32_t Aoff[8];
#pragma unroll
    for (int i = 0; i < 8; ++i) {
        int r = row0 + ldrow + i * 16;
        int rc = (r < n) ? r : (n - 1);
        int t = SHARED ? r : g_etok[g * TOK + rc];
        Aoff[i] = (uint32_t)t * 2048u + (uint32_t)ldch;
    }
    const char* Bp = (const char*)Bbase + (size_t)ldrow * 2048 + ldch;

    int rA = lane & 15, cAb = lane >> 4;
    uint32_t aA0 = (uint32_t)(((wm * 64 + rA) * RSTRB) + cAb * 16);
    int rB = (lane & 7) + ((lane >> 4) << 3), cBb = (lane >> 3) & 1;
    uint32_t aB0 = (uint32_t)A_BYTES + (uint32_t)(((wn * 64 + rB) * RSTRB) + cBb * 16);

    float acc[4][8][4];
#pragma unroll
    for (int i = 0; i < 4; ++i)
#pragma unroll
        for (int j = 0; j < 8; ++j)
#pragma unroll
            for (int k = 0; k < 4; ++k) acc[i][j][k] = 0.f;

    uint32_t af[2][4][4];
    uint32_t bf[2][8][2];

    // prologue
    ISSUE_STAGE(0, 0);
    CP_COMMIT();
    ISSUE_STAGE(1, 128);
    CP_COMMIT();
    CP_WAIT1();
    __syncthreads();
    LD_FRAGS(0, sb, 0);

    for (int ks = 0; ks < NK; ++ks) {
        if (ks + 2 < NK) ISSUE_STAGE((ks + 2) % NSTG, (ks + 2) * 128);
        CP_COMMIT();

        uint32_t stg = sb + (uint32_t)((ks % NSTG) * STG_B);
#pragma unroll
        for (int sub = 0; sub < 4; ++sub) {
            int cur = sub & 1, nxt = cur ^ 1;
            if (sub < 3) {
                LD_FRAGS(nxt, stg, sub + 1);
            } else if (ks + 1 < NK) {
                CP_WAIT1();
                __syncthreads();
                LD_FRAGS(nxt, sb + (uint32_t)(((ks + 1) % NSTG) * STG_B), 0);
            }
            DO_MMAS(cur);
        }
    }

    // epilogue: shared = plain stores (runs first), experts = atomicAdd on top
    int t4 = lane >> 2, t2 = lane & 3;
#pragma unroll
    for (int mt = 0; mt < 4; ++mt) {
#pragma unroll
        for (int h = 0; h < 2; ++h) {
            int r = row0 + wm * 64 + mt * 16 + h * 8 + t4;
            if (SHARED) {
                float* dst = out + (size_t)r * DIM + col0 + wn * 64 + t2 * 2;
#pragma unroll
                for (int nt = 0; nt < 8; ++nt)
                    *(float2*)(dst + nt * 8) =
                        make_float2(acc[mt][nt][2 * h], acc[mt][nt][2 * h + 1]);
            } else if (r < n) {
                int tok = g_etok[g * TOK + r];
                float wt = g_ewt[g * TOK + r];
                float* dst = out + (size_t)tok * DIM + col0 + wn * 64 + t2 * 2;
#pragma unroll
                for (int nt = 0; nt < 8; ++nt) {
                    atomicAdd(dst + nt * 8,     acc[mt][nt][2 * h] * wt);
                    atomicAdd(dst + nt * 8 + 1, acc[mt][nt][2 * h + 1] * wt);
                }
            }
        }
    }

    if (!SHARED) {
        __syncthreads();            // all threads done reading router state
        finish_expert_cta(tid);
    }
}

// ---------------- launch ----------------
extern "C" void kernel_launch(void* const* d_in, const int* in_sizes, int n_in,
                              void* d_out, int out_size) {
    const float* feat = (const float*)d_in[0];
    const float* rw   = (const float*)d_in[1];
    const float* sw   = (const float*)d_in[2];
    const float* ew   = (const float*)d_in[3];
    float* out = (float*)d_out;
    float* aux = out + (out_size - 1);

    cudaFuncSetAttribute(k_gemm<true>, cudaFuncAttributeMaxDynamicSharedMemorySize, SMEM_SZ);
    cudaFuncSetAttribute(k_gemm<false>, cudaFuncAttributeMaxDynamicSharedMemorySize, SMEM_SZ);

    k_prep<<<2176, 256>>>(sw, ew);
    k_router<<<512, 512>>>(feat, rw);
    k_gemm<true><<<dim3(DIM / 128, TOK / 128), 128, SMEM_SZ>>>(out, aux);
    k_gemm<false><<<dim3(DIM / 128, NTILE), 128, SMEM_SZ>>>(out, aux);
}

// round 14
// speedup vs baseline: 1.0515x; 1.0225x over previous
#include <cuda_runtime.h>
#include <cuda_fp16.h>
#include <math.h>
#include <stdint.h>

#define TOK 8192
#define DIM 1024
#define NE  16
#define NTILE 144           // expert row-block grid.y (>= 16384/128 + 16)
#define EGRID (8 * NTILE)   // total expert-gemm CTAs

// ---------------- device scratch (static, allocation-free; zero at load) ----------
__device__ __align__(1024) __half g_wsh[DIM * DIM];         // folded shared weight fp16
__device__ __align__(1024) __half g_xh[TOK * DIM];          // fp16 feat
__device__ __align__(1024) __half g_ewh[NE * DIM * DIM];    // fp16 expert weights
__device__ int   g_ecount[NE];
__device__ float g_pi[NE];
__device__ int   g_cnt[NE];
__device__ int   g_etok[NE * TOK];
__device__ float g_ewt[NE * TOK];
__device__ int   g_done;

__device__ __forceinline__ uint32_t smem_u32(const void* p) {
    uint32_t a;
    asm("{ .reg .u64 t; cvta.to.shared.u64 t, %1; cvt.u32.u64 %0, t; }" : "=r"(a) : "l"(p));
    return a;
}

#define CP16(dst, src) \
    asm volatile("cp.async.cg.shared.global [%0], [%1], 16;" :: "r"(dst), "l"(src) : "memory")
#define CP_COMMIT() asm volatile("cp.async.commit_group;" ::: "memory")
#define CP_WAIT1()  asm volatile("cp.async.wait_group 1;" ::: "memory")

__device__ __forceinline__ uint32_t pack_h2(float a, float b) {
    __half2 h = __floats2half2_rn(a, b);
    return *(uint32_t*)&h;
}

// ---------------- fused router + streaming prep (disjoint block ranges) ----------
// blocks [0,512): router, 16 tokens each
// blocks [512,1024): expert weight fp32->fp16, 8192 float4 each
// blocks [1024,1056): shared weight fold->fp16, 8192 float4 each
__global__ void __launch_bounds__(512) k_work(const float* __restrict__ x,
                                              const float* __restrict__ rw,
                                              const float* __restrict__ sw,
                                              const float* __restrict__ ew) {
    __shared__ float srw[NE * DIM];
    __shared__ float s_pi[NE];
    __shared__ int   s_cnt[NE];
    int tid = threadIdx.x;
    int bid = blockIdx.x;

    if (bid >= 512) {
        if (bid < 1024) {
            int b = bid - 512;
            const float4* e4 = (const float4*)ew;
            uint4* o = (uint4*)g_ewh;
#pragma unroll
            for (int j = 0; j < 8; ++j) {
                int i = b * 8192 + j * 1024 + tid * 2;
                float4 v0 = e4[i];
                float4 v1 = e4[i + 1];
                uint4 u;
                u.x = pack_h2(v0.x, v0.y);
                u.y = pack_h2(v0.z, v0.w);
                u.z = pack_h2(v1.x, v1.y);
                u.w = pack_h2(v1.z, v1.w);
                o[i >> 1] = u;
            }
        } else {
            int b = bid - 1024;
            const float4* s4 = (const float4*)sw;
            const float4* s4b = s4 + (DIM * DIM) / 4;
            uint4* o = (uint4*)g_wsh;
#pragma unroll
            for (int j = 0; j < 8; ++j) {
                int i = b * 8192 + j * 1024 + tid * 2;
                float4 a0 = s4[i],     c0 = s4b[i];
                float4 a1 = s4[i + 1], c1 = s4b[i + 1];
                uint4 u;
                u.x = pack_h2(a0.x + c0.x, a0.y + c0.y);
                u.y = pack_h2(a0.z + c0.z, a0.w + c0.w);
                u.z = pack_h2(a1.x + c1.x, a1.y + c1.y);
                u.w = pack_h2(a1.z + c1.z, a1.w + c1.w);
                o[i >> 1] = u;
            }
        }
        return;
    }

    // ---- router ----
    if (tid < NE) { s_pi[tid] = 0.f; s_cnt[tid] = 0; }
    for (int i = tid; i < NE * DIM; i += 512) srw[i] = rw[i];
    __syncthreads();

    int warp = tid >> 5, lane = tid & 31;
    int t = bid * 16 + warp;
    const float2* xr = (const float2*)(x + (size_t)t * DIM);

    float2 xv[16];
#pragma unroll
    for (int j = 0; j < 16; ++j) xv[j] = xr[lane + 32 * j];

    __half2* xo = (__half2*)g_xh + (size_t)t * (DIM / 2);
#pragma unroll
    for (int j = 0; j < 16; ++j)
        xo[lane + 32 * j] = __floats2half2_rn(xv[j].x, xv[j].y);

    float logit[NE];
#pragma unroll
    for (int e = 0; e < NE; ++e) {
        const float2* w = (const float2*)(srw + e * DIM);
        float s = 0.f;
#pragma unroll
        for (int j = 0; j < 16; ++j) {
            float2 wv = w[lane + 32 * j];
            s += xv[j].x * wv.x + xv[j].y * wv.y;
        }
#pragma unroll
        for (int o = 16; o > 0; o >>= 1) s += __shfl_xor_sync(0xffffffffu, s, o);
        logit[e] = s;
    }

    int e1 = 0; float v1 = logit[0];
#pragma unroll
    for (int e = 1; e < NE; ++e) if (logit[e] > v1) { v1 = logit[e]; e1 = e; }
    int e2 = -1; float v2 = -3.4e38f;
#pragma unroll
    for (int e = 0; e < NE; ++e) if (e != e1 && logit[e] > v2) { v2 = logit[e]; e2 = e; }

    float w1 = 1.f / (1.f + expf(v2 - v1));
    float w2 = 1.f - w1;

    float se = 0.f;
#pragma unroll
    for (int e = 0; e < NE; ++e) se += expf(logit[e] - v1);
    float inv_se = 1.f / se;

    if (lane == 0) {
        atomicAdd(&s_cnt[e1], 1);
        atomicAdd(&s_cnt[e2], 1);
        int p1 = atomicAdd(&g_ecount[e1], 1);
        int p2 = atomicAdd(&g_ecount[e2], 1);
        g_etok[e1 * TOK + p1] = t;  g_ewt[e1 * TOK + p1] = w1;
        g_etok[e2 * TOK + p2] = t;  g_ewt[e2 * TOK + p2] = w2;
#pragma unroll
        for (int e = 0; e < NE; ++e)
            atomicAdd(&s_pi[e], expf(logit[e] - v1) * inv_se);
    }
    __syncthreads();
    if (tid < NE) {
        atomicAdd(&g_pi[tid], s_pi[tid]);
        atomicAdd(&g_cnt[tid], s_cnt[tid]);
    }
}

// ---------------- fp16 mma.sync GEMM: 128 threads, warp tile 64x64 ----------------
#define RSTRB   144
#define A_BYTES (128 * RSTRB)
#define STG_B   (2 * A_BYTES)
#define NSTG    3
#define SMEM_SZ (NSTG * STG_B)
#define NK      (DIM / 64)

#define LD_FRAGS(buf, stgbase, sub)                                                   \
    do {                                                                              \
        uint32_t _sg = (stgbase);                                                     \
        _Pragma("unroll")                                                             \
        for (int mt = 0; mt < 4; ++mt) {                                              \
            uint32_t addr = _sg + aA0 + (uint32_t)(mt * 16 * RSTRB + (sub) * 32);     \
            asm volatile("ldmatrix.sync.aligned.m8n8.x4.shared.b16 {%0,%1,%2,%3}, [%4];" \
                : "=r"(af[buf][mt][0]), "=r"(af[buf][mt][1]),                         \
                  "=r"(af[buf][mt][2]), "=r"(af[buf][mt][3])                          \
                : "r"(addr));                                                         \
        }                                                                             \
        _Pragma("unroll")                                                             \
        for (int p = 0; p < 4; ++p) {                                                 \
            uint32_t addr = _sg + aB0 + (uint32_t)(p * 16 * RSTRB + (sub) * 32);      \
            asm volatile("ldmatrix.sync.aligned.m8n8.x4.shared.b16 {%0,%1,%2,%3}, [%4];" \
                : "=r"(bf[buf][2 * p][0]), "=r"(bf[buf][2 * p][1]),                   \
                  "=r"(bf[buf][2 * p + 1][0]), "=r"(bf[buf][2 * p + 1][1])            \
                : "r"(addr));                                                         \
        }                                                                             \
    } while (0)

#define DO_MMAS(buf)                                                                  \
    do {                                                                              \
        _Pragma("unroll")                                                             \
        for (int mt = 0; mt < 4; ++mt)                                                \
            _Pragma("unroll")                                                         \
            for (int nt = 0; nt < 8; ++nt) {                                          \
                asm volatile(                                                         \
                    "mma.sync.aligned.m16n8k16.row.col.f32.f16.f16.f32 "              \
                    "{%0,%1,%2,%3}, {%4,%5,%6,%7}, {%8,%9}, {%0,%1,%2,%3};"           \
                    : "+f"(acc[mt][nt][0]), "+f"(acc[mt][nt][1]),                     \
                      "+f"(acc[mt][nt][2]), "+f"(acc[mt][nt][3])                      \
                    : "r"(af[buf][mt][0]), "r"(af[buf][mt][1]),                       \
                      "r"(af[buf][mt][2]), "r"(af[buf][mt][3]),                       \
                      "r"(bf[buf][nt][0]), "r"(bf[buf][nt][1]));                      \
            }                                                                         \
    } while (0)

#define ISSUE_STAGE(stgbuf, kb)                                                       \
    do {                                                                              \
        uint32_t so = sb + (uint32_t)((stgbuf) * STG_B);                              \
        _Pragma("unroll")                                                             \
        for (int i = 0; i < 8; ++i) {                                                 \
            CP16(so + dA0 + (uint32_t)(i * 16 * RSTRB),                               \
                 (const char*)g_xh + Aoff[i] + (kb));                                 \
            CP16(so + (uint32_t)A_BYTES + dA0 + (uint32_t)(i * 16 * RSTRB),           \
                 Bp + (size_t)i * 32768 + (kb));                                      \
        }                                                                             \
    } while (0)

__device__ __forceinline__ void finish_expert_cta(int tid) {
    if (tid == 0) {
        int v = atomicAdd(&g_done, 1);
        if (v == EGRID - 1) {
            atomicExch(&g_done, 0);
#pragma unroll
            for (int e = 0; e < NE; ++e) {
                g_ecount[e] = 0;
                g_pi[e] = 0.f;
                g_cnt[e] = 0;
            }
        }
    }
}

template <bool SHARED>
__global__ void __launch_bounds__(128, 2) k_gemm(float* __restrict__ out,
                                                 float* __restrict__ aux_dst) {
    int tid = threadIdx.x;
    int g, n, row0;
    if (SHARED) {
        if (blockIdx.x == 0 && blockIdx.y == 0 && tid == 0) {
            float a = 0.f;
#pragma unroll
            for (int e = 0; e < NE; ++e)
                a += (g_pi[e] / (float)TOK) * ((float)g_cnt[e] / (float)TOK);
            *aux_dst = a;
        }
        g = NE; n = TOK; row0 = blockIdx.y * 128;
    } else {
        int ty = blockIdx.y;
        g = -1; row0 = 0;
        int cum = 0;
#pragma unroll
        for (int e = 0; e < NE; ++e) {
            int ne = g_ecount[e];
            int nb = (ne + 127) >> 7;
            if (g < 0 && ty < cum + nb) { g = e; row0 = (ty - cum) << 7; }
            cum += nb;
        }
        if (g < 0) { finish_expert_cta(tid); return; }
        n = g_ecount[g];
    }
    int col0 = blockIdx.x * 128;

    const __half* Bbase = SHARED ? (g_wsh + (size_t)col0 * DIM)
                                 : (g_ewh + (size_t)g * DIM * DIM + (size_t)col0 * DIM);

    extern __shared__ __align__(1024) char smem[];
    uint32_t sb = smem_u32(smem);
    int wid = tid >> 5, lane = tid & 31;
    int wm = wid & 1, wn = wid >> 1;       // 2x2 warp grid, warp tile 64x64

    int ldrow = tid >> 3;                  // 0..15
    int ldch = (tid & 7) * 16;
    uint32_t dA0 = (uint32_t)(ldrow * RSTRB + ldch);

    uint32_t Aoff[8];
#pragma unroll
    for (int i = 0; i < 8; ++i) {
        int r = row0 + ldrow + i * 16;
        int rc = (r < n) ? r : (n - 1);
        int t = SHARED ? r : g_etok[g * TOK + rc];
        Aoff[i] = (uint32_t)t * 2048u + (uint32_t)ldch;
    }
    const char* Bp = (const char*)Bbase + (size_t)ldrow * 2048 + ldch;

    int rA = lane & 15, cAb = lane >> 4;
    uint32_t aA0 = (uint32_t)(((wm * 64 + rA) * RSTRB) + cAb * 16);
    int rB = (lane & 7) + ((lane >> 4) << 3), cBb = (lane >> 3) & 1;
    uint32_t aB0 = (uint32_t)A_BYTES + (uint32_t)(((wn * 64 + rB) * RSTRB) + cBb * 16);

    float acc[4][8][4];
#pragma unroll
    for (int i = 0; i < 4; ++i)
#pragma unroll
        for (int j = 0; j < 8; ++j)
#pragma unroll
            for (int k = 0; k < 4; ++k) acc[i][j][k] = 0.f;

    uint32_t af[2][4][4];
    uint32_t bf[2][8][2];

    // prologue
    ISSUE_STAGE(0, 0);
    CP_COMMIT();
    ISSUE_STAGE(1, 128);
    CP_COMMIT();
    CP_WAIT1();
    __syncthreads();
    LD_FRAGS(0, sb, 0);

    for (int ks = 0; ks < NK; ++ks) {
        if (ks + 2 < NK) ISSUE_STAGE((ks + 2) % NSTG, (ks + 2) * 128);
        CP_COMMIT();

        uint32_t stg = sb + (uint32_t)((ks % NSTG) * STG_B);
#pragma unroll
        for (int sub = 0; sub < 4; ++sub) {
            int cur = sub & 1, nxt = cur ^ 1;
            if (sub < 3) {
                LD_FRAGS(nxt, stg, sub + 1);
            } else if (ks + 1 < NK) {
                CP_WAIT1();
                __syncthreads();
                LD_FRAGS(nxt, sb + (uint32_t)(((ks + 1) % NSTG) * STG_B), 0);
            }
            DO_MMAS(cur);
        }
    }

    // epilogue: shared = plain stores (runs first), experts = atomicAdd on top
    int t4 = lane >> 2, t2 = lane & 3;
#pragma unroll
    for (int mt = 0; mt < 4; ++mt) {
#pragma unroll
        for (int h = 0; h < 2; ++h) {
            int r = row0 + wm * 64 + mt * 16 + h * 8 + t4;
            if (SHARED) {
                float* dst = out + (size_t)r * DIM + col0 + wn * 64 + t2 * 2;
#pragma unroll
                for (int nt = 0; nt < 8; ++nt)
                    *(float2*)(dst + nt * 8) =
                        make_float2(acc[mt][nt][2 * h], acc[mt][nt][2 * h + 1]);
            } else if (r < n) {
                int tok = g_etok[g * TOK + r];
                float wt = g_ewt[g * TOK + r];
                float* dst = out + (size_t)tok * DIM + col0 + wn * 64 + t2 * 2;
#pragma unroll
                for (int nt = 0; nt < 8; ++nt) {
                    atomicAdd(dst + nt * 8,     acc[mt][nt][2 * h] * wt);
                    atomicAdd(dst + nt * 8 + 1, acc[mt][nt][2 * h + 1] * wt);
                }
            }
        }
    }

    if (!SHARED) {
        __syncthreads();            // all threads done reading router state
        finish_expert_cta(tid);
    }
}

// ---------------- launch ----------------
extern "C" void kernel_launch(void* const* d_in, const int* in_sizes, int n_in,
                              void* d_out, int out_size) {
    const float* feat = (const float*)d_in[0];
    const float* rw   = (const float*)d_in[1];
    const float* sw   = (const float*)d_in[2];
    const float* ew   = (const float*)d_in[3];
    float* out = (float*)d_out;
    float* aux = out + (out_size - 1);

    cudaFuncSetAttribute(k_gemm<true>, cudaFuncAttributeMaxDynamicSharedMemorySize, SMEM_SZ);
    cudaFuncSetAttribute(k_gemm<false>, cudaFuncAttributeMaxDynamicSharedMemorySize, SMEM_SZ);

    k_work<<<1056, 512>>>(feat, rw, sw, ew);
    k_gemm<true><<<dim3(DIM / 128, TOK / 128), 128, SMEM_SZ>>>(out, aux);
    k_gemm<false><<<dim3(DIM / 128, NTILE), 128, SMEM_SZ>>>(out, aux);
}